// round 12
// baseline (speedup 1.0000x reference)
#include <cuda_runtime.h>
#include <math.h>
#include <stdint.h>

#define S_LEN 1024
#define NTOK 2048
#define DMODEL 768
#define NHEAD 12
#define DHEAD 64
#define NEXP 8
#define FF 3072
#define VOCAB 32000

// ---------------- scratch (device globals; no allocation allowed) ----------
__device__ float g_x[NTOK * DMODEL];
__device__ float g_xn[NTOK * DMODEL];
__device__ float g_qkv[NTOK * 3 * DMODEL];
__device__ float g_ctx[NTOK * DMODEL];
__device__ float g_h[(size_t)2 * NTOK * FF];
__device__ float g_yc[2 * NTOK * DMODEL];
__device__ int   g_topi[NTOK * 2];
__device__ float g_topw[NTOK * 2];
__device__ int   g_counts[NEXP];
__device__ int   g_offsets[NEXP];
__device__ int   g_cursor[NEXP];
__device__ int   g_bucket_tok[2 * NTOK];
__device__ int   g_token_rows[NTOK * 2];

__device__ __forceinline__ float gelu_f(float x) {
    return 0.5f * x * (1.0f + erff(x * 0.70710678118654752f));
}

// packed fp32x2 FMA: acc = a * b + acc (per 32-bit lane, IEEE fp32)
__device__ __forceinline__ void fma2(unsigned long long& acc,
                                     unsigned long long a,
                                     unsigned long long b) {
    asm("fma.rn.f32x2 %0, %1, %2, %0;" : "+l"(acc) : "l"(a), "l"(b));
}
__device__ __forceinline__ unsigned long long dup2(float v) {
    unsigned long long r;
    asm("mov.b64 %0, {%1, %1};" : "=l"(r) : "r"(__float_as_uint(v)));
    return r;
}
__device__ __forceinline__ void unpack2(unsigned long long p, float& lo, float& hi) {
    uint32_t a, b;
    asm("mov.b64 {%0, %1}, %2;" : "=r"(a), "=r"(b) : "l"(p));
    lo = __uint_as_float(a); hi = __uint_as_float(b);
}

// ---------------- embedding ----------------
__global__ void embed_kernel(const int* __restrict__ ids,
                             const float* __restrict__ tok,
                             const float* __restrict__ pos) {
    int i = blockIdx.x * blockDim.x + threadIdx.x;
    if (i >= NTOK * DMODEL) return;
    int t = i / DMODEL, d = i - t * DMODEL;
    int s = t & (S_LEN - 1);
    g_x[i] = tok[(size_t)ids[t] * DMODEL + d] + pos[(size_t)s * DMODEL + d];
}

// ---------------- layernorm ----------------
__global__ void ln_kernel(const float* __restrict__ x,
                          const float* __restrict__ g,
                          const float* __restrict__ b,
                          float* __restrict__ y) {
    int row = blockIdx.x;
    const float* xr = x + (size_t)row * DMODEL;
    float s = 0.f, s2 = 0.f;
    for (int d = threadIdx.x; d < DMODEL; d += 256) {
        float v = xr[d]; s += v; s2 += v * v;
    }
    #pragma unroll
    for (int o = 16; o; o >>= 1) {
        s  += __shfl_xor_sync(0xffffffffu, s,  o);
        s2 += __shfl_xor_sync(0xffffffffu, s2, o);
    }
    __shared__ float sh[18];
    int w = threadIdx.x >> 5;
    if ((threadIdx.x & 31) == 0) { sh[w] = s; sh[8 + w] = s2; }
    __syncthreads();
    if (threadIdx.x == 0) {
        float ts = 0.f, ts2 = 0.f;
        #pragma unroll
        for (int i = 0; i < 8; i++) { ts += sh[i]; ts2 += sh[8 + i]; }
        float mean = ts * (1.0f / DMODEL);
        float var = ts2 * (1.0f / DMODEL) - mean * mean;
        sh[16] = mean; sh[17] = rsqrtf(var + 1e-5f);
    }
    __syncthreads();
    float mean = sh[16], inv = sh[17];
    float* yr = y + (size_t)row * DMODEL;
    for (int d = threadIdx.x; d < DMODEL; d += 256)
        yr[d] = (xr[d] - mean) * inv * g[d] + b[d];
}

// ---------------- packed-f32x2 SGEMM body -----------------------------------
// C[M,N] (+bias) = A[M,K]@B[K,N]. 128x128 block, BK=8, 256 thr, 8x8/thread.
// Numerically IDENTICAL to scalar FFMA (IEEE fp32 per lane).
// MODE: 0 = store (+bias if non-null), 1 = gelu(store+bias), 2 = residual add
#define BM 128
#define BN 128
#define BKK 8
template <int MODE, bool GATHER>
__device__ __forceinline__ void sgemm2_body(
    const float* __restrict__ A, const float* __restrict__ Bm,
    const float* __restrict__ bias, float* __restrict__ C,
    int M, int N, int K, const int* __restrict__ gather,
    int rowBase, int colBase)
{
    __shared__ float As[BKK][BM];
    __shared__ float Bs[BKK][BN + 4];   // pad keeps 8B alignment (BN+4 even)
    int tid = threadIdx.x;
    int tx = tid & 15, ty = tid >> 4;

    int am = tid >> 1;
    int ak = (tid & 1) * 4;
    int bk = tid >> 5;
    int bn = (tid & 31) * 4;

    int arow = rowBase + am;
    bool aValid = arow < M;
    size_t arowg;
    if (GATHER) arowg = aValid ? (size_t)gather[rowBase + am] : (size_t)gather[0];
    else        arowg = (size_t)(aValid ? arow : rowBase);
    const float* Aptr = A + arowg * K + ak;
    const float* Bptr = Bm + (size_t)bk * N + colBase + bn;

    unsigned long long acc2[8][4];
    #pragma unroll
    for (int i = 0; i < 8; i++)
        #pragma unroll
        for (int j = 0; j < 4; j++) acc2[i][j] = 0ULL;

    float4 av = aValid ? *(const float4*)(Aptr) : make_float4(0, 0, 0, 0);
    float4 bv = *(const float4*)(Bptr);

    for (int k0 = 0; k0 < K; k0 += BKK) {
        As[ak + 0][am] = av.x; As[ak + 1][am] = av.y;
        As[ak + 2][am] = av.z; As[ak + 3][am] = av.w;
        *(float4*)&Bs[bk][bn] = bv;
        __syncthreads();

        if (k0 + BKK < K) {
            av = aValid ? *(const float4*)(Aptr + k0 + BKK) : make_float4(0, 0, 0, 0);
            bv = *(const float4*)(Bptr + (size_t)(k0 + BKK) * N);
        }

        #pragma unroll
        for (int kk = 0; kk < BKK; kk++) {
            float4 a0 = *(const float4*)&As[kk][ty * 8];
            float4 a1 = *(const float4*)&As[kk][ty * 8 + 4];
            float a[8] = {a0.x, a0.y, a0.z, a0.w, a1.x, a1.y, a1.z, a1.w};
            // 4 packed b-pairs (8 consecutive floats), 8B-aligned
            const unsigned long long* bp =
                (const unsigned long long*)&Bs[kk][tx * 8];
            unsigned long long b0 = bp[0], b1 = bp[1], b2 = bp[2], b3 = bp[3];
            #pragma unroll
            for (int i = 0; i < 8; i++) {
                unsigned long long ad = dup2(a[i]);
                fma2(acc2[i][0], ad, b0);
                fma2(acc2[i][1], ad, b1);
                fma2(acc2[i][2], ad, b2);
                fma2(acc2[i][3], ad, b3);
            }
        }
        __syncthreads();
    }

    #pragma unroll
    for (int i = 0; i < 8; i++) {
        int r = rowBase + ty * 8 + i;
        if (r >= M) continue;
        float* cp = C + (size_t)r * N + colBase + tx * 8;
        #pragma unroll
        for (int j = 0; j < 4; j++) {
            float v0, v1;
            unpack2(acc2[i][j], v0, v1);
            int c = tx * 8 + 2 * j;
            if (bias) { v0 += bias[colBase + c]; v1 += bias[colBase + c + 1]; }
            if (MODE == 1) { v0 = gelu_f(v0); v1 = gelu_f(v1); }
            if (MODE == 2) { cp[2 * j] += v0; cp[2 * j + 1] += v1; }
            else           { cp[2 * j] = v0;  cp[2 * j + 1] = v1; }
        }
    }
}

template <int MODE>
__global__ void __launch_bounds__(256, 2)
sgemm2_kernel(const float* __restrict__ A, const float* __restrict__ Bm,
              const float* __restrict__ bias, float* __restrict__ C,
              int M, int N, int K) {
    sgemm2_body<MODE, false>(A, Bm, bias, C, M, N, K, nullptr,
                             blockIdx.x * BM, blockIdx.y * BN);
}

template <int MODE, bool GATHER>
__global__ void __launch_bounds__(256, 2)
moe2_kernel(const float* __restrict__ A, const float* __restrict__ Bm,
            const float* __restrict__ biasBase, float* __restrict__ C,
            int N, int K) {
    int e = blockIdx.z;
    int M = g_counts[e];
    int rowBase = blockIdx.x * BM;
    if (rowBase >= M) return;
    int off = g_offsets[e];
    const float* Be = Bm + (size_t)e * K * N;
    const float* bias = biasBase + (size_t)e * N;
    float* Ce = C + (size_t)off * N;
    const float* Ae = GATHER ? A : A + (size_t)off * K;
    const int* gat = GATHER ? (g_bucket_tok + off) : nullptr;
    sgemm2_body<MODE, GATHER>(Ae, Be, bias, Ce, M, N, K, gat,
                              rowBase, blockIdx.y * BN);
}

// ---------------- flash attention: 2 threads per query (Dh split 32/32) -----
__global__ void __launch_bounds__(128)
attn_kernel(const float* __restrict__ qkv, float* __restrict__ ctx) {
    int qt = blockIdx.x;        // 0..15 (64 queries per block)
    int h  = blockIdx.y;        // 0..11
    int b  = blockIdx.z;        // 0..1
    int tid = threadIdx.x;
    int qlocal = tid >> 1;
    int half = tid & 1;
    int q = qt * 64 + qlocal;
    int tok = b * S_LEN + q;

    __shared__ float ksh[64][64];
    __shared__ float vsh[64][64];

    const float scale = 0.125f;
    float qreg[32];
    const float* qp = qkv + (size_t)tok * (3 * DMODEL) + h * 64 + half * 32;
    #pragma unroll
    for (int d = 0; d < 32; d += 4) {
        float4 v = *(const float4*)(qp + d);
        qreg[d] = v.x * scale; qreg[d + 1] = v.y * scale;
        qreg[d + 2] = v.z * scale; qreg[d + 3] = v.w * scale;
    }

    float m = -1e30f, l = 0.f;
    float acc[32];
    #pragma unroll
    for (int d = 0; d < 32; d++) acc[d] = 0.f;

    int blockMaxQ = qt * 64 + 63;
    for (int j0 = 0; j0 <= blockMaxQ; j0 += 64) {
        for (int idx = tid; idx < 64 * 16; idx += 128) {
            int r = idx >> 4;
            int c = (idx & 15) * 4;
            size_t base = (size_t)(b * S_LEN + j0 + r) * (3 * DMODEL) + h * 64 + c;
            *(float4*)&ksh[r][c] = *(const float4*)(qkv + base + DMODEL);
            *(float4*)&vsh[r][c] = *(const float4*)(qkv + base + 2 * DMODEL);
        }
        __syncthreads();
        #pragma unroll 1
        for (int j = 0; j < 64; j++) {
            float sp = 0.f;
            const float* kr = &ksh[j][half * 32];
            #pragma unroll
            for (int d = 0; d < 32; d++) sp += qreg[d] * kr[d];
            float s = sp + __shfl_xor_sync(0xffffffffu, sp, 1);
            s = (j0 + j <= q) ? s : -1e30f;
            if (s > m) {
                float corr = expf(m - s);
                l *= corr;
                #pragma unroll
                for (int d = 0; d < 32; d++) acc[d] *= corr;
                m = s;
            }
            float p = expf(s - m);
            l += p;
            const float* vr = &vsh[j][half * 32];
            #pragma unroll
            for (int d = 0; d < 32; d++) acc[d] += p * vr[d];
        }
        __syncthreads();
    }

    float inv = 1.0f / l;
    float* op = ctx + (size_t)tok * DMODEL + h * 64 + half * 32;
    #pragma unroll
    for (int d = 0; d < 32; d++) op[d] = acc[d] * inv;
}

// ---------------- router: softmax + top-2 ----------------
__global__ void zero_counts_kernel() {
    if (threadIdx.x < NEXP) g_counts[threadIdx.x] = 0;
}

__global__ void router_kernel(const float* __restrict__ xn,
                              const float* __restrict__ Rw) {
    int t = blockIdx.x * 8 + (threadIdx.x >> 5);
    int lane = threadIdx.x & 31;
    if (t >= NTOK) return;
    float acc[NEXP];
    #pragma unroll
    for (int e = 0; e < NEXP; e++) acc[e] = 0.f;
    const float* xr = xn + (size_t)t * DMODEL;
    for (int d = lane; d < DMODEL; d += 32) {
        float xv = xr[d];
        const float* rp = Rw + (size_t)d * NEXP;
        #pragma unroll
        for (int e = 0; e < NEXP; e++) acc[e] += xv * rp[e];
    }
    #pragma unroll
    for (int e = 0; e < NEXP; e++)
        #pragma unroll
        for (int o = 16; o; o >>= 1) acc[e] += __shfl_xor_sync(0xffffffffu, acc[e], o);
    if (lane == 0) {
        float mx = acc[0];
        #pragma unroll
        for (int e = 1; e < NEXP; e++) mx = fmaxf(mx, acc[e]);
        float p[NEXP], sum = 0.f;
        #pragma unroll
        for (int e = 0; e < NEXP; e++) { p[e] = expf(acc[e] - mx); sum += p[e]; }
        float invs = 1.0f / sum;
        #pragma unroll
        for (int e = 0; e < NEXP; e++) p[e] *= invs;
        int i0 = 0;
        #pragma unroll
        for (int e = 1; e < NEXP; e++) if (p[e] > p[i0]) i0 = e;
        int i1 = (i0 == 0) ? 1 : 0;
        #pragma unroll
        for (int e = 0; e < NEXP; e++) if (e != i0 && p[e] > p[i1]) i1 = e;
        float w0 = p[i0], w1 = p[i1], ws = 1.0f / (w0 + w1);
        g_topi[t * 2] = i0; g_topi[t * 2 + 1] = i1;
        g_topw[t * 2] = w0 * ws; g_topw[t * 2 + 1] = w1 * ws;
        atomicAdd(&g_counts[i0], 1);
        atomicAdd(&g_counts[i1], 1);
    }
}

__global__ void scan_kernel() {
    int off = 0;
    for (int e = 0; e < NEXP; e++) {
        g_offsets[e] = off;
        off += g_counts[e];
        g_cursor[e] = 0;
    }
}

__global__ void assign_kernel() {
    int t = blockIdx.x * blockDim.x + threadIdx.x;
    if (t >= NTOK) return;
    #pragma unroll
    for (int k = 0; k < 2; k++) {
        int e = g_topi[t * 2 + k];
        int p = atomicAdd(&g_cursor[e], 1);
        int r = g_offsets[e] + p;
        g_bucket_tok[r] = t;
        g_token_rows[t * 2 + k] = r;
    }
}

__global__ void combine_kernel(float* __restrict__ x) {
    int i = blockIdx.x * blockDim.x + threadIdx.x;
    if (i >= NTOK * DMODEL) return;
    int t = i / DMODEL, d = i - t * DMODEL;
    int r0 = g_token_rows[t * 2], r1 = g_token_rows[t * 2 + 1];
    x[i] += g_topw[t * 2] * g_yc[(size_t)r0 * DMODEL + d]
          + g_topw[t * 2 + 1] * g_yc[(size_t)r1 * DMODEL + d];
}

// ---------------- host orchestration ----------------
extern "C" void kernel_launch(void* const* d_in, const int* in_sizes, int n_in,
                              void* d_out, int out_size) {
    const int*   ids   = (const int*)d_in[0];
    const float* tok   = (const float*)d_in[1];
    const float* pos   = (const float*)d_in[2];
    const float* ln1g  = (const float*)d_in[3];
    const float* ln1b  = (const float*)d_in[4];
    const float* wqkv  = (const float*)d_in[5];
    const float* bqkv  = (const float*)d_in[6];
    const float* wo    = (const float*)d_in[7];
    const float* bo    = (const float*)d_in[8];
    const float* ln2g  = (const float*)d_in[9];
    const float* ln2b  = (const float*)d_in[10];
    const float* rw    = (const float*)d_in[11];
    const float* w1    = (const float*)d_in[12];
    const float* b1    = (const float*)d_in[13];
    const float* w2    = (const float*)d_in[14];
    const float* b2    = (const float*)d_in[15];
    const float* lnfg  = (const float*)d_in[16];
    const float* lnfb  = (const float*)d_in[17];
    const float* wout  = (const float*)d_in[18];
    float* out = (float*)d_out;

    float* xptr;   cudaGetSymbolAddress((void**)&xptr,  g_x);
    float* xnptr;  cudaGetSymbolAddress((void**)&xnptr, g_xn);
    float* qkvp;   cudaGetSymbolAddress((void**)&qkvp,  g_qkv);
    float* ctxp;   cudaGetSymbolAddress((void**)&ctxp,  g_ctx);
    float* hp;     cudaGetSymbolAddress((void**)&hp,    g_h);
    float* ycp;    cudaGetSymbolAddress((void**)&ycp,   g_yc);

    embed_kernel<<<(NTOK * DMODEL + 255) / 256, 256>>>(ids, tok, pos);

    for (int l = 0; l < 2; l++) {
        ln_kernel<<<NTOK, 256>>>(xptr, ln1g + l * DMODEL, ln1b + l * DMODEL, xnptr);
        sgemm2_kernel<0><<<dim3(16, 18), 256>>>(
            xnptr, wqkv + (size_t)l * DMODEL * 3 * DMODEL, bqkv + (size_t)l * 3 * DMODEL,
            qkvp, NTOK, 3 * DMODEL, DMODEL);
        attn_kernel<<<dim3(16, NHEAD, 2), 128>>>(qkvp, ctxp);
        sgemm2_kernel<2><<<dim3(16, 6), 256>>>(
            ctxp, wo + (size_t)l * DMODEL * DMODEL, bo + (size_t)l * DMODEL,
            xptr, NTOK, DMODEL, DMODEL);
        ln_kernel<<<NTOK, 256>>>(xptr, ln2g + l * DMODEL, ln2b + l * DMODEL, xnptr);
        zero_counts_kernel<<<1, 32>>>();
        router_kernel<<<NTOK / 8, 256>>>(xnptr, rw + (size_t)l * DMODEL * NEXP);
        scan_kernel<<<1, 1>>>();
        assign_kernel<<<NTOK / 256, 256>>>();
        moe2_kernel<1, true><<<dim3(16, FF / BN, NEXP), 256>>>(
            xnptr, w1 + (size_t)l * NEXP * DMODEL * FF, b1 + (size_t)l * NEXP * FF,
            hp, FF, DMODEL);
        moe2_kernel<0, false><<<dim3(16, DMODEL / BN, NEXP), 256>>>(
            hp, w2 + (size_t)l * NEXP * FF * DMODEL, b2 + (size_t)l * NEXP * DMODEL,
            ycp, DMODEL, FF);
        combine_kernel<<<(NTOK * DMODEL + 255) / 256, 256>>>(xptr);
    }

    ln_kernel<<<NTOK, 256>>>(xptr, lnfg, lnfb, xnptr);
    sgemm2_kernel<0><<<dim3(16, VOCAB / BN), 256>>>(
        xnptr, wout, nullptr, out, NTOK, VOCAB, DMODEL);
}

// round 13
// speedup vs baseline: 1.0047x; 1.0047x over previous
#include <cuda_runtime.h>
#include <math.h>
#include <stdint.h>

#define S_LEN 1024
#define NTOK 2048
#define DMODEL 768
#define NHEAD 12
#define DHEAD 64
#define NEXP 8
#define FF 3072
#define VOCAB 32000

// ---------------- scratch (device globals; no allocation allowed) ----------
__device__ float g_x[NTOK * DMODEL];
__device__ float g_xn[NTOK * DMODEL];
__device__ float g_qkv[NTOK * 3 * DMODEL];
__device__ float g_ctx[NTOK * DMODEL];
__device__ float g_h[(size_t)2 * NTOK * FF];
__device__ float g_yc[2 * NTOK * DMODEL];
__device__ int   g_topi[NTOK * 2];
__device__ float g_topw[NTOK * 2];
__device__ int   g_counts[NEXP];
__device__ int   g_offsets[NEXP];
__device__ int   g_cursor[NEXP];
__device__ int   g_bucket_tok[2 * NTOK];
__device__ int   g_token_rows[NTOK * 2];

__device__ __forceinline__ float gelu_f(float x) {
    return 0.5f * x * (1.0f + erff(x * 0.70710678118654752f));
}

// packed fp32x2 FMA: acc = a * b + acc (per 32-bit lane, IEEE fp32)
__device__ __forceinline__ void fma2(unsigned long long& acc,
                                     unsigned long long a,
                                     unsigned long long b) {
    asm("fma.rn.f32x2 %0, %1, %2, %0;" : "+l"(acc) : "l"(a), "l"(b));
}
__device__ __forceinline__ unsigned long long dup2(float v) {
    unsigned long long r;
    asm("mov.b64 %0, {%1, %1};" : "=l"(r) : "r"(__float_as_uint(v)));
    return r;
}
__device__ __forceinline__ void unpack2(unsigned long long p, float& lo, float& hi) {
    uint32_t a, b;
    asm("mov.b64 {%0, %1}, %2;" : "=r"(a), "=r"(b) : "l"(p));
    lo = __uint_as_float(a); hi = __uint_as_float(b);
}

// ---------------- embedding ----------------
__global__ void embed_kernel(const int* __restrict__ ids,
                             const float* __restrict__ tok,
                             const float* __restrict__ pos) {
    int i = blockIdx.x * blockDim.x + threadIdx.x;
    if (i >= NTOK * DMODEL) return;
    int t = i / DMODEL, d = i - t * DMODEL;
    int s = t & (S_LEN - 1);
    g_x[i] = tok[(size_t)ids[t] * DMODEL + d] + pos[(size_t)s * DMODEL + d];
}

// ---------------- layernorm ----------------
__global__ void ln_kernel(const float* __restrict__ x,
                          const float* __restrict__ g,
                          const float* __restrict__ b,
                          float* __restrict__ y) {
    int row = blockIdx.x;
    const float* xr = x + (size_t)row * DMODEL;
    float s = 0.f, s2 = 0.f;
    for (int d = threadIdx.x; d < DMODEL; d += 256) {
        float v = xr[d]; s += v; s2 += v * v;
    }
    #pragma unroll
    for (int o = 16; o; o >>= 1) {
        s  += __shfl_xor_sync(0xffffffffu, s,  o);
        s2 += __shfl_xor_sync(0xffffffffu, s2, o);
    }
    __shared__ float sh[18];
    int w = threadIdx.x >> 5;
    if ((threadIdx.x & 31) == 0) { sh[w] = s; sh[8 + w] = s2; }
    __syncthreads();
    if (threadIdx.x == 0) {
        float ts = 0.f, ts2 = 0.f;
        #pragma unroll
        for (int i = 0; i < 8; i++) { ts += sh[i]; ts2 += sh[8 + i]; }
        float mean = ts * (1.0f / DMODEL);
        float var = ts2 * (1.0f / DMODEL) - mean * mean;
        sh[16] = mean; sh[17] = rsqrtf(var + 1e-5f);
    }
    __syncthreads();
    float mean = sh[16], inv = sh[17];
    float* yr = y + (size_t)row * DMODEL;
    for (int d = threadIdx.x; d < DMODEL; d += 256)
        yr[d] = (xr[d] - mean) * inv * g[d] + b[d];
}

// ---------------- packed-f32x2 SGEMM body -----------------------------------
// C[M,N] (+bias) = A[M,K]@B[K,N]. 128x128 block, BK=8, 256 thr, 8x8/thread.
// Numerically IDENTICAL to scalar FFMA (IEEE fp32 per lane).
// MODE: 0 = store (+bias if non-null), 1 = gelu(store+bias), 2 = residual add
#define BM 128
#define BN 128
#define BKK 8
template <int MODE, bool GATHER>
__device__ __forceinline__ void sgemm2_body(
    const float* __restrict__ A, const float* __restrict__ Bm,
    const float* __restrict__ bias, float* __restrict__ C,
    int M, int N, int K, const int* __restrict__ gather,
    int rowBase, int colBase)
{
    __shared__ float As[BKK][BM];
    __shared__ float Bs[BKK][BN + 4];   // pad keeps 8B alignment (BN+4 even)
    int tid = threadIdx.x;
    int tx = tid & 15, ty = tid >> 4;

    int am = tid >> 1;
    int ak = (tid & 1) * 4;
    int bk = tid >> 5;
    int bn = (tid & 31) * 4;

    int arow = rowBase + am;
    bool aValid = arow < M;
    size_t arowg;
    if (GATHER) arowg = aValid ? (size_t)gather[rowBase + am] : (size_t)gather[0];
    else        arowg = (size_t)(aValid ? arow : rowBase);
    const float* Aptr = A + arowg * K + ak;
    const float* Bptr = Bm + (size_t)bk * N + colBase + bn;

    unsigned long long acc2[8][4];
    #pragma unroll
    for (int i = 0; i < 8; i++)
        #pragma unroll
        for (int j = 0; j < 4; j++) acc2[i][j] = 0ULL;

    float4 av = aValid ? *(const float4*)(Aptr) : make_float4(0, 0, 0, 0);
    float4 bv = *(const float4*)(Bptr);

    for (int k0 = 0; k0 < K; k0 += BKK) {
        As[ak + 0][am] = av.x; As[ak + 1][am] = av.y;
        As[ak + 2][am] = av.z; As[ak + 3][am] = av.w;
        *(float4*)&Bs[bk][bn] = bv;
        __syncthreads();

        if (k0 + BKK < K) {
            av = aValid ? *(const float4*)(Aptr + k0 + BKK) : make_float4(0, 0, 0, 0);
            bv = *(const float4*)(Bptr + (size_t)(k0 + BKK) * N);
        }

        #pragma unroll
        for (int kk = 0; kk < BKK; kk++) {
            float4 a0 = *(const float4*)&As[kk][ty * 8];
            float4 a1 = *(const float4*)&As[kk][ty * 8 + 4];
            float a[8] = {a0.x, a0.y, a0.z, a0.w, a1.x, a1.y, a1.z, a1.w};
            // 4 packed b-pairs (8 consecutive floats), 8B-aligned
            const unsigned long long* bp =
                (const unsigned long long*)&Bs[kk][tx * 8];
            unsigned long long b0 = bp[0], b1 = bp[1], b2 = bp[2], b3 = bp[3];
            #pragma unroll
            for (int i = 0; i < 8; i++) {
                unsigned long long ad = dup2(a[i]);
                fma2(acc2[i][0], ad, b0);
                fma2(acc2[i][1], ad, b1);
                fma2(acc2[i][2], ad, b2);
                fma2(acc2[i][3], ad, b3);
            }
        }
        __syncthreads();
    }

    #pragma unroll
    for (int i = 0; i < 8; i++) {
        int r = rowBase + ty * 8 + i;
        if (r >= M) continue;
        float* cp = C + (size_t)r * N + colBase + tx * 8;
        #pragma unroll
        for (int j = 0; j < 4; j++) {
            float v0, v1;
            unpack2(acc2[i][j], v0, v1);
            int c = tx * 8 + 2 * j;
            if (bias) { v0 += bias[colBase + c]; v1 += bias[colBase + c + 1]; }
            if (MODE == 1) { v0 = gelu_f(v0); v1 = gelu_f(v1); }
            if (MODE == 2) { cp[2 * j] += v0; cp[2 * j + 1] += v1; }
            else           { cp[2 * j] = v0;  cp[2 * j + 1] = v1; }
        }
    }
}

template <int MODE>
__global__ void __launch_bounds__(256, 2)
sgemm2_kernel(const float* __restrict__ A, const float* __restrict__ Bm,
              const float* __restrict__ bias, float* __restrict__ C,
              int M, int N, int K) {
    sgemm2_body<MODE, false>(A, Bm, bias, C, M, N, K, nullptr,
                             blockIdx.x * BM, blockIdx.y * BN);
}

template <int MODE, bool GATHER>
__global__ void __launch_bounds__(256, 2)
moe2_kernel(const float* __restrict__ A, const float* __restrict__ Bm,
            const float* __restrict__ biasBase, float* __restrict__ C,
            int N, int K) {
    int e = blockIdx.z;
    int M = g_counts[e];
    int rowBase = blockIdx.x * BM;
    if (rowBase >= M) return;
    int off = g_offsets[e];
    const float* Be = Bm + (size_t)e * K * N;
    const float* bias = biasBase + (size_t)e * N;
    float* Ce = C + (size_t)off * N;
    const float* Ae = GATHER ? A : A + (size_t)off * K;
    const int* gat = GATHER ? (g_bucket_tok + off) : nullptr;
    sgemm2_body<MODE, GATHER>(Ae, Be, bias, Ce, M, N, K, gat,
                              rowBase, blockIdx.y * BN);
}

// ---------------- flash attention: 2 threads per query (Dh split 32/32) -----
__global__ void __launch_bounds__(128)
attn_kernel(const float* __restrict__ qkv, float* __restrict__ ctx) {
    int qt = blockIdx.x;        // 0..15 (64 queries per block)
    int h  = blockIdx.y;        // 0..11
    int b  = blockIdx.z;        // 0..1
    int tid = threadIdx.x;
    int qlocal = tid >> 1;
    int half = tid & 1;
    int q = qt * 64 + qlocal;
    int tok = b * S_LEN + q;

    __shared__ float ksh[64][64];
    __shared__ float vsh[64][64];

    const float scale = 0.125f;
    float qreg[32];
    const float* qp = qkv + (size_t)tok * (3 * DMODEL) + h * 64 + half * 32;
    #pragma unroll
    for (int d = 0; d < 32; d += 4) {
        float4 v = *(const float4*)(qp + d);
        qreg[d] = v.x * scale; qreg[d + 1] = v.y * scale;
        qreg[d + 2] = v.z * scale; qreg[d + 3] = v.w * scale;
    }

    float m = -1e30f, l = 0.f;
    float acc[32];
    #pragma unroll
    for (int d = 0; d < 32; d++) acc[d] = 0.f;

    int blockMaxQ = qt * 64 + 63;
    for (int j0 = 0; j0 <= blockMaxQ; j0 += 64) {
        for (int idx = tid; idx < 64 * 16; idx += 128) {
            int r = idx >> 4;
            int c = (idx & 15) * 4;
            size_t base = (size_t)(b * S_LEN + j0 + r) * (3 * DMODEL) + h * 64 + c;
            *(float4*)&ksh[r][c] = *(const float4*)(qkv + base + DMODEL);
            *(float4*)&vsh[r][c] = *(const float4*)(qkv + base + 2 * DMODEL);
        }
        __syncthreads();
        #pragma unroll 1
        for (int j = 0; j < 64; j++) {
            float sp = 0.f;
            const float* kr = &ksh[j][half * 32];
            #pragma unroll
            for (int d = 0; d < 32; d++) sp += qreg[d] * kr[d];
            float s = sp + __shfl_xor_sync(0xffffffffu, sp, 1);
            s = (j0 + j <= q) ? s : -1e30f;
            if (s > m) {
                float corr = expf(m - s);
                l *= corr;
                #pragma unroll
                for (int d = 0; d < 32; d++) acc[d] *= corr;
                m = s;
            }
            float p = expf(s - m);
            l += p;
            const float* vr = &vsh[j][half * 32];
            #pragma unroll
            for (int d = 0; d < 32; d++) acc[d] += p * vr[d];
        }
        __syncthreads();
    }

    float inv = 1.0f / l;
    float* op = ctx + (size_t)tok * DMODEL + h * 64 + half * 32;
    #pragma unroll
    for (int d = 0; d < 32; d++) op[d] = acc[d] * inv;
}

// ---------------- router: softmax + top-2 ----------------
__global__ void zero_counts_kernel() {
    if (threadIdx.x < NEXP) g_counts[threadIdx.x] = 0;
}

__global__ void router_kernel(const float* __restrict__ xn,
                              const float* __restrict__ Rw) {
    int t = blockIdx.x * 8 + (threadIdx.x >> 5);
    int lane = threadIdx.x & 31;
    if (t >= NTOK) return;
    float acc[NEXP];
    #pragma unroll
    for (int e = 0; e < NEXP; e++) acc[e] = 0.f;
    const float* xr = xn + (size_t)t * DMODEL;
    for (int d = lane; d < DMODEL; d += 32) {
        float xv = xr[d];
        const float* rp = Rw + (size_t)d * NEXP;
        #pragma unroll
        for (int e = 0; e < NEXP; e++) acc[e] += xv * rp[e];
    }
    #pragma unroll
    for (int e = 0; e < NEXP; e++)
        #pragma unroll
        for (int o = 16; o; o >>= 1) acc[e] += __shfl_xor_sync(0xffffffffu, acc[e], o);
    if (lane == 0) {
        float mx = acc[0];
        #pragma unroll
        for (int e = 1; e < NEXP; e++) mx = fmaxf(mx, acc[e]);
        float p[NEXP], sum = 0.f;
        #pragma unroll
        for (int e = 0; e < NEXP; e++) { p[e] = expf(acc[e] - mx); sum += p[e]; }
        float invs = 1.0f / sum;
        #pragma unroll
        for (int e = 0; e < NEXP; e++) p[e] *= invs;
        int i0 = 0;
        #pragma unroll
        for (int e = 1; e < NEXP; e++) if (p[e] > p[i0]) i0 = e;
        int i1 = (i0 == 0) ? 1 : 0;
        #pragma unroll
        for (int e = 0; e < NEXP; e++) if (e != i0 && p[e] > p[i1]) i1 = e;
        float w0 = p[i0], w1 = p[i1], ws = 1.0f / (w0 + w1);
        g_topi[t * 2] = i0; g_topi[t * 2 + 1] = i1;
        g_topw[t * 2] = w0 * ws; g_topw[t * 2 + 1] = w1 * ws;
        atomicAdd(&g_counts[i0], 1);
        atomicAdd(&g_counts[i1], 1);
    }
}

__global__ void scan_kernel() {
    int off = 0;
    for (int e = 0; e < NEXP; e++) {
        g_offsets[e] = off;
        off += g_counts[e];
        g_cursor[e] = 0;
    }
}

__global__ void assign_kernel() {
    int t = blockIdx.x * blockDim.x + threadIdx.x;
    if (t >= NTOK) return;
    #pragma unroll
    for (int k = 0; k < 2; k++) {
        int e = g_topi[t * 2 + k];
        int p = atomicAdd(&g_cursor[e], 1);
        int r = g_offsets[e] + p;
        g_bucket_tok[r] = t;
        g_token_rows[t * 2 + k] = r;
    }
}

__global__ void combine_kernel(float* __restrict__ x) {
    int i = blockIdx.x * blockDim.x + threadIdx.x;
    if (i >= NTOK * DMODEL) return;
    int t = i / DMODEL, d = i - t * DMODEL;
    int r0 = g_token_rows[t * 2], r1 = g_token_rows[t * 2 + 1];
    x[i] += g_topw[t * 2] * g_yc[(size_t)r0 * DMODEL + d]
          + g_topw[t * 2 + 1] * g_yc[(size_t)r1 * DMODEL + d];
}

// ---------------- host orchestration ----------------
extern "C" void kernel_launch(void* const* d_in, const int* in_sizes, int n_in,
                              void* d_out, int out_size) {
    const int*   ids   = (const int*)d_in[0];
    const float* tok   = (const float*)d_in[1];
    const float* pos   = (const float*)d_in[2];
    const float* ln1g  = (const float*)d_in[3];
    const float* ln1b  = (const float*)d_in[4];
    const float* wqkv  = (const float*)d_in[5];
    const float* bqkv  = (const float*)d_in[6];
    const float* wo    = (const float*)d_in[7];
    const float* bo    = (const float*)d_in[8];
    const float* ln2g  = (const float*)d_in[9];
    const float* ln2b  = (const float*)d_in[10];
    const float* rw    = (const float*)d_in[11];
    const float* w1    = (const float*)d_in[12];
    const float* b1    = (const float*)d_in[13];
    const float* w2    = (const float*)d_in[14];
    const float* b2    = (const float*)d_in[15];
    const float* lnfg  = (const float*)d_in[16];
    const float* lnfb  = (const float*)d_in[17];
    const float* wout  = (const float*)d_in[18];
    float* out = (float*)d_out;

    float* xptr;   cudaGetSymbolAddress((void**)&xptr,  g_x);
    float* xnptr;  cudaGetSymbolAddress((void**)&xnptr, g_xn);
    float* qkvp;   cudaGetSymbolAddress((void**)&qkvp,  g_qkv);
    float* ctxp;   cudaGetSymbolAddress((void**)&ctxp,  g_ctx);
    float* hp;     cudaGetSymbolAddress((void**)&hp,    g_h);
    float* ycp;    cudaGetSymbolAddress((void**)&ycp,   g_yc);

    embed_kernel<<<(NTOK * DMODEL + 255) / 256, 256>>>(ids, tok, pos);

    for (int l = 0; l < 2; l++) {
        ln_kernel<<<NTOK, 256>>>(xptr, ln1g + l * DMODEL, ln1b + l * DMODEL, xnptr);
        sgemm2_kernel<0><<<dim3(16, 18), 256>>>(
            xnptr, wqkv + (size_t)l * DMODEL * 3 * DMODEL, bqkv + (size_t)l * 3 * DMODEL,
            qkvp, NTOK, 3 * DMODEL, DMODEL);
        attn_kernel<<<dim3(16, NHEAD, 2), 128>>>(qkvp, ctxp);
        sgemm2_kernel<2><<<dim3(16, 6), 256>>>(
            ctxp, wo + (size_t)l * DMODEL * DMODEL, bo + (size_t)l * DMODEL,
            xptr, NTOK, DMODEL, DMODEL);
        ln_kernel<<<NTOK, 256>>>(xptr, ln2g + l * DMODEL, ln2b + l * DMODEL, xnptr);
        zero_counts_kernel<<<1, 32>>>();
        router_kernel<<<NTOK / 8, 256>>>(xnptr, rw + (size_t)l * DMODEL * NEXP);
        scan_kernel<<<1, 1>>>();
        assign_kernel<<<NTOK / 256, 256>>>();
        moe2_kernel<1, true><<<dim3(16, FF / BN, NEXP), 256>>>(
            xnptr, w1 + (size_t)l * NEXP * DMODEL * FF, b1 + (size_t)l * NEXP * FF,
            hp, FF, DMODEL);
        moe2_kernel<0, false><<<dim3(16, DMODEL / BN, NEXP), 256>>>(
            hp, w2 + (size_t)l * NEXP * FF * DMODEL, b2 + (size_t)l * NEXP * DMODEL,
            ycp, DMODEL, FF);
        combine_kernel<<<(NTOK * DMODEL + 255) / 256, 256>>>(xptr);
    }

    ln_kernel<<<NTOK, 256>>>(xptr, lnfg, lnfb, xnptr);
    sgemm2_kernel<0><<<dim3(16, VOCAB / BN), 256>>>(
        xnptr, wout, nullptr, out, NTOK, VOCAB, DMODEL);
}